// round 8
// baseline (speedup 1.0000x reference)
#include <cuda_runtime.h>
#include <math.h>

#define BATCH 32
#define NTOK 1024
#define CDIM 1024
#define NHEADS 16
#define HD 64
#define AGENTS 49
#define LOG2E 1.4426950408889634f

typedef unsigned long long u64;

// ---------------- precomputed small tensors ----------------
__device__ float g_part[3 * 16 * 4 * CDIM];  // j-split partials of [w|b] @ wq/wk/wv
__device__ float g_W[8][CDIM];               // rows 0-3: Q-path (w0,w1,w2,bias); 4-7: K-path
__device__ float g_G[NHEADS][3][3];          // Wv_h @ w_proj_h
__device__ float g_Et[3][3][3];              // dwc tap x rank-i x out-j
__device__ float g_Ebt[3][3];                // dwc tap bias terms
__device__ float g_Const[3];                 // constant per output channel
__device__ __align__(8) float g_b1s[AGENTS * NTOK];  // bias1 * log2(e)
__device__ float g_pool[BATCH][AGENTS][3];   // pooled raw Q
__device__ float4 g_cq[BATCH * NHEADS * AGENTS];  // stage-2 coeffs (log2-scaled)
__device__ float4 g_gv[BATCH * NHEADS * AGENTS];  // normalized (pv·G_h)/sum

__device__ __forceinline__ float warp_sum(float v) {
    #pragma unroll
    for (int o = 16; o; o >>= 1) v += __shfl_xor_sync(0xffffffffu, v, o);
    return v;
}
__device__ __forceinline__ u64 pack2(float lo, float hi) {
    u64 r;
    asm("mov.b64 %0, {%1, %2};" : "=l"(r) : "f"(lo), "f"(hi));
    return r;
}
__device__ __forceinline__ void unpack2(u64 v, float& lo, float& hi) {
    asm("mov.b64 {%0, %1}, %2;" : "=f"(lo), "=f"(hi) : "l"(v));
}
__device__ __forceinline__ u64 fma2(u64 a, u64 b, u64 c) {
    u64 r;
    asm("fma.rn.f32x2 %0, %1, %2, %3;" : "=l"(r) : "l"(a), "l"(b), "l"(c));
    return r;
}
__device__ __forceinline__ u64 add2(u64 a, u64 b) {
    u64 r;
    asm("add.rn.f32x2 %0, %1, %2;" : "=l"(r) : "l"(a), "l"(b));
    return r;
}

// 2^x for |x| <= 1 via degree-5 polynomial (Taylor in ln2); err < 3e-6 at |x|=1,
// < 1e-7 for |x| < 0.5. Scores here are provably < 0.3 in magnitude.
#define EP1 0.69314718056f
#define EP2 0.24022650700f
#define EP3 0.05550410866f
#define EP4 0.00961812911f
#define EP5 0.00133335581f
__device__ __forceinline__ float exp2poly(float x) {
    float p = fmaf(x, EP5, EP4);
    p = fmaf(x, p, EP3);
    p = fmaf(x, p, EP2);
    p = fmaf(x, p, EP1);
    return fmaf(x, p, 1.0f);
}
__device__ __forceinline__ u64 exp2poly2(u64 x, u64 C1, u64 C2, u64 C3, u64 C4,
                                         u64 C5, u64 ONE) {
    u64 p = fma2(x, C5, C4);
    p = fma2(x, p, C3);
    p = fma2(x, p, C2);
    p = fma2(x, p, C1);
    return fma2(x, p, ONE);
}

// ---------------------------------------------------------------------------
// prepA: partial fold of [w_vel|b_vel] @ {wq,wk,wv}, j split 16x (64 each).
// ---------------------------------------------------------------------------
__global__ __launch_bounds__(256) void prepA(
    const float* __restrict__ w_vel, const float* __restrict__ b_vel,
    const float* __restrict__ w_init, const float* __restrict__ b_init,
    const float* __restrict__ wq, const float* __restrict__ wk,
    const float* __restrict__ wv) {
    int mat = blockIdx.z, jz = blockIdx.y;
    int c = blockIdx.x * 256 + threadIdx.x;
    const float* W = (mat == 0) ? wq : (mat == 1 ? wk : wv);
    const float* A = (mat == 0) ? w_vel : w_init;
    const float* bb = (mat == 0) ? b_vel : b_init;
    float a0 = 0.f, a1 = 0.f, a2 = 0.f, a3 = 0.f;
    int j0 = jz * 64;
    #pragma unroll 8
    for (int j = j0; j < j0 + 64; j++) {
        float w = W[j * CDIM + c];
        a0 = fmaf(__ldg(A + j), w, a0);
        a1 = fmaf(__ldg(A + CDIM + j), w, a1);
        a2 = fmaf(__ldg(A + 2 * CDIM + j), w, a2);
        a3 = fmaf(__ldg(bb + j), w, a3);
    }
    float* p = g_part + ((mat * 16 + jz) * 4) * CDIM + c;
    p[0] = a0; p[CDIM] = a1; p[2 * CDIM] = a2; p[3 * CDIM] = a3;
}

// ---------------------------------------------------------------------------
// prepB (same partition as R5/R6)
// ---------------------------------------------------------------------------
__global__ __launch_bounds__(256) void prepB(
    const float* __restrict__ Q,
    const float* __restrict__ bq, const float* __restrict__ bk,
    const float* __restrict__ bv,
    const float* __restrict__ bias1,
    const float* __restrict__ dwc_w, const float* __restrict__ dwc_b,
    const float* __restrict__ w_proj, const float* __restrict__ b_proj) {
    const int blk = blockIdx.x;
    const int tid = threadIdx.x;
    const int lane = tid & 31, warp = tid >> 5;

    if (blk < 32) {
        int gid = blk * 256 + tid;
        int mat = gid >> 12;
        int r = (gid >> 10) & 3;
        int c = gid & 1023;
        float s = 0.f;
        #pragma unroll
        for (int jz = 0; jz < 16; jz++)
            s += g_part[((mat * 16 + jz) * 4 + r) * CDIM + c];
        if (r == 3) s += (mat == 0 ? bq : bk)[c];
        g_W[mat * 4 + r][c] = s;
    } else if (blk < 64) {
        int b = blk - 32;
        const float* Qb = Q + (size_t)b * NTOK * 3;
        for (int a = warp; a < AGENTS; a += 8) {
            int s = (a * NTOK) / AGENTS;
            int e = ((a + 1) * NTOK + AGENTS - 1) / AGENTS;
            int cnt = (e - s) * 3;
            float ac0 = 0.f, ac1 = 0.f, ac2 = 0.f;
            #pragma unroll
            for (int k = 0; k < 3; k++) {
                int idx = lane + 32 * k;
                if (idx < cnt) {
                    float v = Qb[s * 3 + idx];
                    int c = idx % 3;
                    ac0 += (c == 0) ? v : 0.f;
                    ac1 += (c == 1) ? v : 0.f;
                    ac2 += (c == 2) ? v : 0.f;
                }
            }
            ac0 = warp_sum(ac0); ac1 = warp_sum(ac1); ac2 = warp_sum(ac2);
            if (lane == 0) {
                float inv = 1.f / (float)(e - s);
                g_pool[b][a][0] = ac0 * inv;
                g_pool[b][a][1] = ac1 * inv;
                g_pool[b][a][2] = ac2 * inv;
            }
        }
    } else if (blk < 87) {
        int wg = (blk - 64) * 8 + warp;
        float acc = 0.f;
        if (wg < 27) {
            int t = wg / 9, rem = wg % 9, i = rem / 3, j = rem % 3;
            for (int c = lane; c < CDIM; c += 32) {
                float wv_i = 0.f;
                #pragma unroll
                for (int jz = 0; jz < 16; jz++)
                    wv_i += g_part[((32 + jz) * 4 + i) * CDIM + c];
                acc = fmaf(dwc_w[c * 9 + t * 3 + 1] * wv_i, w_proj[c * 3 + j], acc);
            }
            acc = warp_sum(acc);
            if (lane == 0) g_Et[t][i][j] = acc;
        } else if (wg < 36) {
            int t = (wg - 27) / 3, j = (wg - 27) % 3;
            for (int c = lane; c < CDIM; c += 32) {
                float wvb = bv[c];
                #pragma unroll
                for (int jz = 0; jz < 16; jz++)
                    wvb += g_part[((32 + jz) * 4 + 3) * CDIM + c];
                acc = fmaf(dwc_w[c * 9 + t * 3 + 1] * wvb, w_proj[c * 3 + j], acc);
            }
            acc = warp_sum(acc);
            if (lane == 0) g_Ebt[t][j] = acc;
        } else if (wg < 39) {
            int j = wg - 36;
            for (int c = lane; c < CDIM; c += 32) {
                float wvb = bv[c] + dwc_b[c];
                #pragma unroll
                for (int jz = 0; jz < 16; jz++)
                    wvb += g_part[((32 + jz) * 4 + 3) * CDIM + c];
                acc = fmaf(wvb, w_proj[c * 3 + j], acc);
            }
            acc = warp_sum(acc);
            if (lane == 0) g_Const[j] = acc + b_proj[j];
        } else if (wg < 183) {
            int g = wg - 39;
            int h = g / 9, rem = g % 9, i = rem / 3, j = rem % 3;
            #pragma unroll
            for (int k = 0; k < 2; k++) {
                int d = lane + 32 * k;
                int c = h * HD + d;
                float wv_i = 0.f;
                #pragma unroll
                for (int jz = 0; jz < 16; jz++)
                    wv_i += g_part[((32 + jz) * 4 + i) * CDIM + c];
                acc = fmaf(wv_i, w_proj[c * 3 + j], acc);
            }
            acc = warp_sum(acc);
            if (lane == 0) g_G[h][i][j] = acc;
        }
    } else {
        int base = (blk - 87) * 2048;
        #pragma unroll
        for (int k = 0; k < 8; k++) {
            int idx = base + k * 256 + tid;
            if (idx < AGENTS * NTOK) g_b1s[idx] = bias1[idx] * LOG2E;
        }
    }
}

// ---------------------------------------------------------------------------
// stage1 v4: per (b,h), 256 threads / 8 warps. SoA K/V in smem; token PAIRS
// via f32x2 (scalar score, packed poly-exp + packed accumulate, LDG.64 b1).
// Warp w: agents 6w..6w+5 over all tokens; agent 48 spread 128 tokens/warp.
// ---------------------------------------------------------------------------
__global__ __launch_bounds__(256, 2) void stage1(
    const float* __restrict__ Kg_all, const float* __restrict__ Vg_all) {
    __shared__ float sKx[NTOK], sKy[NTOK], sKz[NTOK];
    __shared__ float sVx[NTOK], sVy[NTOK], sVz[NTOK];
    __shared__ float sW[8][HD];
    __shared__ float sCkM[4][4], sCqM[4][4];
    __shared__ float4 sCk[AGENTS];
    __shared__ float sG[9];
    __shared__ float s48[8][4];

    const int tid = threadIdx.x;
    const int h = blockIdx.x, b = blockIdx.y;
    const float* Kg = Kg_all + (size_t)b * NTOK * 3;
    const float* Vg = Vg_all + (size_t)b * NTOK * 3;

    for (int n = tid; n < NTOK; n += 256) {
        const float* kp = Kg + n * 3;
        const float* vp = Vg + n * 3;
        sKx[n] = kp[0]; sKy[n] = kp[1]; sKz[n] = kp[2];
        sVx[n] = vp[0]; sVy[n] = vp[1]; sVz[n] = vp[2];
    }
    for (int idx = tid; idx < 8 * HD; idx += 256) {
        int r = idx >> 6, d = idx & 63;
        sW[r][d] = g_W[r][h * HD + d];
    }
    if (tid >= 247) {
        int q = tid - 247;
        sG[q] = g_G[h][q / 3][q % 3];
    }
    __syncthreads();

    if (tid < 32) {
        int q = tid & 15;
        int j = q >> 2, i = q & 3;
        const float* rq = sW[j];
        const float* rx = (tid < 16) ? sW[4 + i] : sW[i];
        float s = 0.f;
        #pragma unroll 8
        for (int d = 0; d < HD; d++) s = fmaf(rq[d], rx[d], s);
        if (tid < 16) sCkM[j][i] = s; else sCqM[j][i] = s;
    }
    __syncthreads();

    if (tid < AGENTS) {
        int a = tid;
        float p0 = g_pool[b][a][0], p1 = g_pool[b][a][1], p2 = g_pool[b][a][2];
        float ck[4], cq[4];
        #pragma unroll
        for (int i = 0; i < 4; i++) {
            ck[i] = LOG2E * (sCkM[3][i] + p0 * sCkM[0][i] + p1 * sCkM[1][i] + p2 * sCkM[2][i]);
            cq[i] = LOG2E * (sCqM[3][i] + p0 * sCqM[0][i] + p1 * sCqM[1][i] + p2 * sCqM[2][i]);
        }
        sCk[a] = make_float4(ck[0], ck[1], ck[2], ck[3]);
        g_cq[(b * NHEADS + h) * AGENTS + a] = make_float4(cq[0], cq[1], cq[2], cq[3]);
    }
    __syncthreads();

    const u64 C1 = pack2(EP1, EP1), C2 = pack2(EP2, EP2), C3 = pack2(EP3, EP3);
    const u64 C4 = pack2(EP4, EP4), C5 = pack2(EP5, EP5), ONE = pack2(1.f, 1.f);
    const u64 ZERO = pack2(0.f, 0.f);

    const int w = tid >> 5, lane = tid & 31;
    const int a0 = w * 6;
    const u64* Kx = (const u64*)sKx;
    const u64* Ky = (const u64*)sKy;
    const u64* Kz = (const u64*)sKz;
    const u64* Vx = (const u64*)sVx;
    const u64* Vy = (const u64*)sVy;
    const u64* Vz = (const u64*)sVz;

    float4 ck[6];
    u64 su[6], p0[6], p1[6], p2[6];
    #pragma unroll
    for (int t = 0; t < 6; t++) {
        ck[t] = sCk[a0 + t];
        su[t] = ZERO; p0[t] = ZERO; p1[t] = ZERO; p2[t] = ZERO;
    }
    #pragma unroll 2
    for (int jj = 0; jj < 16; jj++) {
        int i = jj * 32 + lane;
        u64 kx2 = Kx[i], ky2 = Ky[i], kz2 = Kz[i];
        u64 vx2 = Vx[i], vy2 = Vy[i], vz2 = Vz[i];
        float kxl, kxh, kyl, kyh, kzl, kzh;
        unpack2(kx2, kxl, kxh);
        unpack2(ky2, kyl, kyh);
        unpack2(kz2, kzl, kzh);
        #pragma unroll
        for (int t = 0; t < 6; t++) {
            float2 b1 = __ldg(((const float2*)(g_b1s + (a0 + t) * NTOK)) + i);
            float sl = fmaf(ck[t].x, kxl, fmaf(ck[t].y, kyl, fmaf(ck[t].z, kzl, ck[t].w + b1.x)));
            float sh = fmaf(ck[t].x, kxh, fmaf(ck[t].y, kyh, fmaf(ck[t].z, kzh, ck[t].w + b1.y)));
            u64 e2 = exp2poly2(pack2(sl, sh), C1, C2, C3, C4, C5, ONE);
            su[t] = add2(su[t], e2);
            p0[t] = fma2(e2, vx2, p0[t]);
            p1[t] = fma2(e2, vy2, p1[t]);
            p2[t] = fma2(e2, vz2, p2[t]);
        }
    }

    // agent 48: warp w covers pair indices [64w, 64w+64) = 128 tokens
    {
        float4 c48 = sCk[48];
        u64 s8 = ZERO, q0 = ZERO, q1 = ZERO, q2 = ZERO;
        #pragma unroll
        for (int t2 = 0; t2 < 2; t2++) {
            int i = w * 64 + t2 * 32 + lane;
            u64 kx2 = Kx[i], ky2 = Ky[i], kz2 = Kz[i];
            float kxl, kxh, kyl, kyh, kzl, kzh;
            unpack2(kx2, kxl, kxh);
            unpack2(ky2, kyl, kyh);
            unpack2(kz2, kzl, kzh);
            float2 b1 = __ldg(((const float2*)(g_b1s + 48 * NTOK)) + i);
            float sl = fmaf(c48.x, kxl, fmaf(c48.y, kyl, fmaf(c48.z, kzl, c48.w + b1.x)));
            float sh = fmaf(c48.x, kxh, fmaf(c48.y, kyh, fmaf(c48.z, kzh, c48.w + b1.y)));
            u64 e2 = exp2poly2(pack2(sl, sh), C1, C2, C3, C4, C5, ONE);
            s8 = add2(s8, e2);
            q0 = fma2(e2, Vx[i], q0);
            q1 = fma2(e2, Vy[i], q1);
            q2 = fma2(e2, Vz[i], q2);
        }
        float al, ah;
        unpack2(s8, al, ah);
        float xu = warp_sum(al + ah);
        unpack2(q0, al, ah);
        float x0 = warp_sum(al + ah);
        unpack2(q1, al, ah);
        float x1 = warp_sum(al + ah);
        unpack2(q2, al, ah);
        float x2 = warp_sum(al + ah);
        if (lane == 0) {
            s48[w][0] = xu; s48[w][1] = x0; s48[w][2] = x1; s48[w][3] = x2;
        }
    }

    #pragma unroll
    for (int t = 0; t < 6; t++) {
        float al, ah;
        unpack2(su[t], al, ah);
        float s = warp_sum(al + ah);
        unpack2(p0[t], al, ah);
        float q0 = warp_sum(al + ah);
        unpack2(p1[t], al, ah);
        float q1 = warp_sum(al + ah);
        unpack2(p2[t], al, ah);
        float q2 = warp_sum(al + ah);
        if (lane == 0) {
            float inv = 1.f / s;
            float gv0 = (q0 * sG[0] + q1 * sG[3] + q2 * sG[6]) * inv;
            float gv1 = (q0 * sG[1] + q1 * sG[4] + q2 * sG[7]) * inv;
            float gv2 = (q0 * sG[2] + q1 * sG[5] + q2 * sG[8]) * inv;
            g_gv[(b * NHEADS + h) * AGENTS + a0 + t] = make_float4(gv0, gv1, gv2, 0.f);
        }
    }
    __syncthreads();
    if (w == 0) {
        float xu = (lane < 8) ? s48[lane][0] : 0.f;
        float x0 = (lane < 8) ? s48[lane][1] : 0.f;
        float x1 = (lane < 8) ? s48[lane][2] : 0.f;
        float x2 = (lane < 8) ? s48[lane][3] : 0.f;
        xu = warp_sum(xu); x0 = warp_sum(x0); x1 = warp_sum(x1); x2 = warp_sum(x2);
        if (lane == 0) {
            float inv = 1.f / xu;
            float gv0 = (x0 * sG[0] + x1 * sG[3] + x2 * sG[6]) * inv;
            float gv1 = (x0 * sG[1] + x1 * sG[4] + x2 * sG[7]) * inv;
            float gv2 = (x0 * sG[2] + x1 * sG[5] + x2 * sG[8]) * inv;
            g_gv[(b * NHEADS + h) * AGENTS + 48] = make_float4(gv0, gv1, gv2, 0.f);
        }
    }
}

// ---------------------------------------------------------------------------
// stage2 (R5 structure): CTA = (b, 64-token tile). 16 warps = heads, lane =
// token, 2 groups/warp; MUFU-free via scalar exp2 polynomial.
// ---------------------------------------------------------------------------
__global__ __launch_bounds__(512) void stage2(
    const float* __restrict__ Qg_all, const float* __restrict__ Vg_all,
    const float* __restrict__ bias2, float* __restrict__ out) {
    __shared__ float4 scq[NHEADS * AGENTS];
    __shared__ float4 sgv[NHEADS * AGENTS];
    __shared__ float sb2[AGENTS * 65];       // padded: bank = (a + nn) % 32
    __shared__ float sred[NHEADS][32][3];

    const int tid = threadIdx.x;
    const int b = blockIdx.y;
    const int h = tid >> 5, lane = tid & 31;
    const int t0 = blockIdx.x * 64;

    for (int i = tid; i < NHEADS * AGENTS; i += 512) {
        scq[i] = g_cq[b * NHEADS * AGENTS + i];
        sgv[i] = g_gv[b * NHEADS * AGENTS + i];
    }
    for (int i = tid; i < 64 * AGENTS; i += 512) {
        int nn = i / AGENTS, a = i % AGENTS;
        sb2[a * 65 + nn] = bias2[(size_t)(t0 + nn) * AGENTS + a] * LOG2E;
    }
    __syncthreads();

    float q0[2], q1[2], q2[2];
    #pragma unroll
    for (int g = 0; g < 2; g++) {
        const float* qp = Qg_all + (size_t)b * NTOK * 3 + (t0 + g * 32 + lane) * 3;
        q0[g] = qp[0]; q1[g] = qp[1]; q2[g] = qp[2];
    }

    float su[2] = {0.f, 0.f};
    float u0[2] = {0.f, 0.f}, u1[2] = {0.f, 0.f}, u2[2] = {0.f, 0.f};
    const float4* cqh = scq + h * AGENTS;
    const float4* gvh = sgv + h * AGENTS;
    #pragma unroll 7
    for (int a = 0; a < AGENTS; a++) {
        float4 cq = cqh[a];
        float4 gv = gvh[a];
        #pragma unroll
        for (int g = 0; g < 2; g++) {
            float b2v = sb2[a * 65 + (g << 5) + lane];
            float s = fmaf(cq.x, q0[g], fmaf(cq.y, q1[g], fmaf(cq.z, q2[g], cq.w + b2v)));
            float e = exp2poly(s);
            su[g] += e;
            u0[g] = fmaf(e, gv.x, u0[g]);
            u1[g] = fmaf(e, gv.y, u1[g]);
            u2[g] = fmaf(e, gv.z, u2[g]);
        }
    }

    #pragma unroll
    for (int g = 0; g < 2; g++) {
        float inv = 1.f / su[g];
        sred[h][lane][0] = u0[g] * inv;
        sred[h][lane][1] = u1[g] * inv;
        sred[h][lane][2] = u2[g] * inv;
        __syncthreads();
        if (tid < 96) {
            int j = tid >> 5, tk = tid & 31;
            int nn = t0 + g * 32 + tk;
            float r = g_Const[j];
            #pragma unroll
            for (int hh = 0; hh < NHEADS; hh++) r += sred[hh][tk][j];
            const float* Vb = Vg_all + (size_t)b * NTOK * 3;
            #pragma unroll
            for (int t = 0; t < 3; t++) {
                int mrow = nn - 1 + t;
                if (mrow >= 0 && mrow < NTOK) {
                    const float* vp = Vb + mrow * 3;
                    r += g_Ebt[t][j];
                    r = fmaf(vp[0], g_Et[t][0][j], r);
                    r = fmaf(vp[1], g_Et[t][1][j], r);
                    r = fmaf(vp[2], g_Et[t][2][j], r);
                }
            }
            out[(size_t)b * 3 * NTOK + j * NTOK + nn] = r;
        }
        __syncthreads();
    }
}

extern "C" void kernel_launch(void* const* d_in, const int* in_sizes, int n_in,
                              void* d_out, int out_size) {
    const float* Q      = (const float*)d_in[0];
    const float* K      = (const float*)d_in[1];
    const float* V      = (const float*)d_in[2];
    const float* w_vel  = (const float*)d_in[3];
    const float* b_vel  = (const float*)d_in[4];
    const float* w_init = (const float*)d_in[5];
    const float* b_init = (const float*)d_in[6];
    const float* wq     = (const float*)d_in[7];
    const float* bq     = (const float*)d_in[8];
    const float* wk     = (const float*)d_in[9];
    const float* bk     = (const float*)d_in[10];
    const float* wv     = (const float*)d_in[11];
    const float* bv     = (const float*)d_in[12];
    const float* ab1    = (const float*)d_in[13];
    const float* ab2    = (const float*)d_in[14];
    const float* dwc_w  = (const float*)d_in[15];
    const float* dwc_b  = (const float*)d_in[16];
    const float* w_proj = (const float*)d_in[17];
    const float* b_proj = (const float*)d_in[18];
    float* out = (float*)d_out;

    prepA<<<dim3(4, 16, 3), 256>>>(w_vel, b_vel, w_init, b_init, wq, wk, wv);
    prepB<<<112, 256>>>(Q, bq, bk, bv, ab1, dwc_w, dwc_b, w_proj, b_proj);
    stage1<<<dim3(NHEADS, BATCH), 256>>>(K, V);
    stage2<<<dim3(16, BATCH), 512>>>(Q, V, ab2, out);
}

// round 10
// speedup vs baseline: 1.1482x; 1.1482x over previous
#include <cuda_runtime.h>
#include <math.h>

#define BATCH 32
#define NTOK 1024
#define CDIM 1024
#define NHEADS 16
#define HD 64
#define AGENTS 49
#define LOG2E 1.4426950408889634f

typedef unsigned long long u64;

// ---------------- precomputed small tensors ----------------
__device__ float g_part[3 * 16 * 4 * CDIM];  // j-split partials of [w|b] @ wq/wk/wv
__device__ float g_W[8][CDIM];               // rows 0-3: Q-path (w0,w1,w2,bias); 4-7: K-path
__device__ float g_G[NHEADS][3][3];          // Wv_h @ w_proj_h
__device__ float g_Et[3][3][3];              // dwc tap x rank-i x out-j
__device__ float g_Ebt[3][3];                // dwc tap bias terms
__device__ float g_Const[3];                 // constant per output channel
__device__ __align__(8) float g_b1s[AGENTS * NTOK];  // bias1 * log2(e)
__device__ float g_pool[BATCH][AGENTS][3];   // pooled raw Q
__device__ float4 g_cq[BATCH * NHEADS * AGENTS];  // stage-2 coeffs (log2-scaled)
__device__ float4 g_gv[BATCH * NHEADS * AGENTS];  // normalized (pv·G_h)/sum

__device__ __forceinline__ float warp_sum(float v) {
    #pragma unroll
    for (int o = 16; o; o >>= 1) v += __shfl_xor_sync(0xffffffffu, v, o);
    return v;
}
__device__ __forceinline__ float ex2(float x) {
    float r;
    asm("ex2.approx.ftz.f32 %0, %1;" : "=f"(r) : "f"(x));
    return r;
}
__device__ __forceinline__ u64 pack2(float lo, float hi) {
    u64 r;
    asm("mov.b64 %0, {%1, %2};" : "=l"(r) : "f"(lo), "f"(hi));
    return r;
}
__device__ __forceinline__ void unpack2(u64 v, float& lo, float& hi) {
    asm("mov.b64 {%0, %1}, %2;" : "=f"(lo), "=f"(hi) : "l"(v));
}
__device__ __forceinline__ u64 fma2(u64 a, u64 b, u64 c) {
    u64 r;
    asm("fma.rn.f32x2 %0, %1, %2, %3;" : "=l"(r) : "l"(a), "l"(b), "l"(c));
    return r;
}
__device__ __forceinline__ u64 add2(u64 a, u64 b) {
    u64 r;
    asm("add.rn.f32x2 %0, %1, %2;" : "=l"(r) : "l"(a), "l"(b));
    return r;
}

// ---------------------------------------------------------------------------
// prepA: partial fold of [w_vel|b_vel] @ {wq,wk,wv}, j split 16x (64 each).
// ---------------------------------------------------------------------------
__global__ __launch_bounds__(256) void prepA(
    const float* __restrict__ w_vel, const float* __restrict__ b_vel,
    const float* __restrict__ w_init, const float* __restrict__ b_init,
    const float* __restrict__ wq, const float* __restrict__ wk,
    const float* __restrict__ wv) {
    int mat = blockIdx.z, jz = blockIdx.y;
    int c = blockIdx.x * 256 + threadIdx.x;
    const float* W = (mat == 0) ? wq : (mat == 1 ? wk : wv);
    const float* A = (mat == 0) ? w_vel : w_init;
    const float* bb = (mat == 0) ? b_vel : b_init;
    float a0 = 0.f, a1 = 0.f, a2 = 0.f, a3 = 0.f;
    int j0 = jz * 64;
    #pragma unroll 8
    for (int j = j0; j < j0 + 64; j++) {
        float w = W[j * CDIM + c];
        a0 = fmaf(__ldg(A + j), w, a0);
        a1 = fmaf(__ldg(A + CDIM + j), w, a1);
        a2 = fmaf(__ldg(A + 2 * CDIM + j), w, a2);
        a3 = fmaf(__ldg(bb + j), w, a3);
    }
    float* p = g_part + ((mat * 16 + jz) * 4) * CDIM + c;
    p[0] = a0; p[CDIM] = a1; p[2 * CDIM] = a2; p[3 * CDIM] = a3;
}

// ---------------------------------------------------------------------------
// prepB
// ---------------------------------------------------------------------------
__global__ __launch_bounds__(256) void prepB(
    const float* __restrict__ Q,
    const float* __restrict__ bq, const float* __restrict__ bk,
    const float* __restrict__ bv,
    const float* __restrict__ bias1,
    const float* __restrict__ dwc_w, const float* __restrict__ dwc_b,
    const float* __restrict__ w_proj, const float* __restrict__ b_proj) {
    const int blk = blockIdx.x;
    const int tid = threadIdx.x;
    const int lane = tid & 31, warp = tid >> 5;

    if (blk < 32) {
        int gid = blk * 256 + tid;
        int mat = gid >> 12;
        int r = (gid >> 10) & 3;
        int c = gid & 1023;
        float s = 0.f;
        #pragma unroll
        for (int jz = 0; jz < 16; jz++)
            s += g_part[((mat * 16 + jz) * 4 + r) * CDIM + c];
        if (r == 3) s += (mat == 0 ? bq : bk)[c];
        g_W[mat * 4 + r][c] = s;
    } else if (blk < 64) {
        int b = blk - 32;
        const float* Qb = Q + (size_t)b * NTOK * 3;
        for (int a = warp; a < AGENTS; a += 8) {
            int s = (a * NTOK) / AGENTS;
            int e = ((a + 1) * NTOK + AGENTS - 1) / AGENTS;
            int cnt = (e - s) * 3;
            float ac0 = 0.f, ac1 = 0.f, ac2 = 0.f;
            #pragma unroll
            for (int k = 0; k < 3; k++) {
                int idx = lane + 32 * k;
                if (idx < cnt) {
                    float v = Qb[s * 3 + idx];
                    int c = idx % 3;
                    ac0 += (c == 0) ? v : 0.f;
                    ac1 += (c == 1) ? v : 0.f;
                    ac2 += (c == 2) ? v : 0.f;
                }
            }
            ac0 = warp_sum(ac0); ac1 = warp_sum(ac1); ac2 = warp_sum(ac2);
            if (lane == 0) {
                float inv = 1.f / (float)(e - s);
                g_pool[b][a][0] = ac0 * inv;
                g_pool[b][a][1] = ac1 * inv;
                g_pool[b][a][2] = ac2 * inv;
            }
        }
    } else if (blk < 87) {
        int wg = (blk - 64) * 8 + warp;
        float acc = 0.f;
        if (wg < 27) {
            int t = wg / 9, rem = wg % 9, i = rem / 3, j = rem % 3;
            for (int c = lane; c < CDIM; c += 32) {
                float wv_i = 0.f;
                #pragma unroll
                for (int jz = 0; jz < 16; jz++)
                    wv_i += g_part[((32 + jz) * 4 + i) * CDIM + c];
                acc = fmaf(dwc_w[c * 9 + t * 3 + 1] * wv_i, w_proj[c * 3 + j], acc);
            }
            acc = warp_sum(acc);
            if (lane == 0) g_Et[t][i][j] = acc;
        } else if (wg < 36) {
            int t = (wg - 27) / 3, j = (wg - 27) % 3;
            for (int c = lane; c < CDIM; c += 32) {
                float wvb = bv[c];
                #pragma unroll
                for (int jz = 0; jz < 16; jz++)
                    wvb += g_part[((32 + jz) * 4 + 3) * CDIM + c];
                acc = fmaf(dwc_w[c * 9 + t * 3 + 1] * wvb, w_proj[c * 3 + j], acc);
            }
            acc = warp_sum(acc);
            if (lane == 0) g_Ebt[t][j] = acc;
        } else if (wg < 39) {
            int j = wg - 36;
            for (int c = lane; c < CDIM; c += 32) {
                float wvb = bv[c] + dwc_b[c];
                #pragma unroll
                for (int jz = 0; jz < 16; jz++)
                    wvb += g_part[((32 + jz) * 4 + 3) * CDIM + c];
                acc = fmaf(wvb, w_proj[c * 3 + j], acc);
            }
            acc = warp_sum(acc);
            if (lane == 0) g_Const[j] = acc + b_proj[j];
        } else if (wg < 183) {
            int g = wg - 39;
            int h = g / 9, rem = g % 9, i = rem / 3, j = rem % 3;
            #pragma unroll
            for (int k = 0; k < 2; k++) {
                int d = lane + 32 * k;
                int c = h * HD + d;
                float wv_i = 0.f;
                #pragma unroll
                for (int jz = 0; jz < 16; jz++)
                    wv_i += g_part[((32 + jz) * 4 + i) * CDIM + c];
                acc = fmaf(wv_i, w_proj[c * 3 + j], acc);
            }
            acc = warp_sum(acc);
            if (lane == 0) g_G[h][i][j] = acc;
        }
    } else {
        int base = (blk - 87) * 2048;
        #pragma unroll
        for (int k = 0; k < 8; k++) {
            int idx = base + k * 256 + tid;
            if (idx < AGENTS * NTOK) g_b1s[idx] = bias1[idx] * LOG2E;
        }
    }
}

// ---------------------------------------------------------------------------
// stage1 (R5-proven): per (b,h). 7 warps x 7 agents each; one K/V load
// serves 7 scores. Stores cq (log2-scaled) and gv = (pv·G_h)/sum per agent.
// ---------------------------------------------------------------------------
__global__ __launch_bounds__(256) void stage1(
    const float* __restrict__ Kg_all, const float* __restrict__ Vg_all) {
    __shared__ float4 sK[NTOK];
    __shared__ float4 sV[NTOK];
    __shared__ float sW[8][HD];
    __shared__ float sCkM[4][4], sCqM[4][4];
    __shared__ float4 sCk[AGENTS];
    __shared__ float sG[9];

    const int tid = threadIdx.x;
    const int h = blockIdx.x, b = blockIdx.y;
    const float* Kg = Kg_all + (size_t)b * NTOK * 3;
    const float* Vg = Vg_all + (size_t)b * NTOK * 3;

    for (int idx = tid; idx < 8 * HD; idx += 256) {
        int r = idx >> 6, d = idx & 63;
        sW[r][d] = g_W[r][h * HD + d];
    }
    for (int n = tid; n < NTOK; n += 256) {
        const float* kp = Kg + n * 3;
        const float* vp = Vg + n * 3;
        sK[n] = make_float4(kp[0], kp[1], kp[2], 0.f);
        sV[n] = make_float4(vp[0], vp[1], vp[2], 0.f);
    }
    if (tid >= 128 && tid < 137) {
        int q = tid - 128;
        sG[q] = g_G[h][q / 3][q % 3];
    }
    __syncthreads();

    if (tid < 32) {
        int q = tid & 15;
        int j = q >> 2, i = q & 3;
        const float* rq = sW[j];
        const float* rx = (tid < 16) ? sW[4 + i] : sW[i];
        float s = 0.f;
        #pragma unroll 8
        for (int d = 0; d < HD; d++) s = fmaf(rq[d], rx[d], s);
        if (tid < 16) sCkM[j][i] = s; else sCqM[j][i] = s;
    }
    __syncthreads();

    if (tid < AGENTS) {
        int a = tid;
        float p0 = g_pool[b][a][0], p1 = g_pool[b][a][1], p2 = g_pool[b][a][2];
        float ck[4], cq[4];
        #pragma unroll
        for (int i = 0; i < 4; i++) {
            ck[i] = LOG2E * (sCkM[3][i] + p0 * sCkM[0][i] + p1 * sCkM[1][i] + p2 * sCkM[2][i]);
            cq[i] = LOG2E * (sCqM[3][i] + p0 * sCqM[0][i] + p1 * sCqM[1][i] + p2 * sCqM[2][i]);
        }
        sCk[a] = make_float4(ck[0], ck[1], ck[2], ck[3]);
        g_cq[(b * NHEADS + h) * AGENTS + a] = make_float4(cq[0], cq[1], cq[2], cq[3]);
    }
    __syncthreads();

    const int warp = tid >> 5, lane = tid & 31;
    if (warp < 7) {
        const int a0 = warp * 7;
        float4 ck[7];
        float sum[7], p0[7], p1[7], p2[7];
        #pragma unroll
        for (int i = 0; i < 7; i++) {
            ck[i] = sCk[a0 + i];
            sum[i] = 0.f; p0[i] = 0.f; p1[i] = 0.f; p2[i] = 0.f;
        }
        #pragma unroll 4
        for (int jj = 0; jj < 32; jj++) {
            int n = jj * 32 + lane;
            float4 k = sK[n];
            float4 v = sV[n];
            #pragma unroll
            for (int i = 0; i < 7; i++) {
                float b1v = __ldg(g_b1s + (a0 + i) * NTOK + n);
                float s = fmaf(ck[i].x, k.x, fmaf(ck[i].y, k.y, fmaf(ck[i].z, k.z, ck[i].w + b1v)));
                float e = ex2(s);
                sum[i] += e;
                p0[i] = fmaf(e, v.x, p0[i]);
                p1[i] = fmaf(e, v.y, p1[i]);
                p2[i] = fmaf(e, v.z, p2[i]);
            }
        }
        #pragma unroll
        for (int i = 0; i < 7; i++) {
            float su = warp_sum(sum[i]);
            float q0 = warp_sum(p0[i]);
            float q1 = warp_sum(p1[i]);
            float q2 = warp_sum(p2[i]);
            if (lane == 0) {
                float inv = 1.f / su;
                float gv0 = (q0 * sG[0] + q1 * sG[3] + q2 * sG[6]) * inv;
                float gv1 = (q0 * sG[1] + q1 * sG[4] + q2 * sG[7]) * inv;
                float gv2 = (q0 * sG[2] + q1 * sG[5] + q2 * sG[8]) * inv;
                g_gv[(b * NHEADS + h) * AGENTS + a0 + i] = make_float4(gv0, gv1, gv2, 0.f);
            }
        }
    }
}

// ---------------------------------------------------------------------------
// stage2 (R6 f32x2, smem-slimmed for 2 CTAs/SM): CTA = (b, 128-token tile).
// 16 warps = heads, lane = token, 4 groups per warp packed pairwise into
// f32x2. Single-sync wide epilogue.
// ---------------------------------------------------------------------------
__global__ __launch_bounds__(512, 2) void stage2(
    const float* __restrict__ Qg_all, const float* __restrict__ Vg_all,
    const float* __restrict__ bias2, float* __restrict__ out) {
    __shared__ float4 scq[NHEADS * AGENTS];
    __shared__ float4 sgv[NHEADS * AGENTS];
    __shared__ float2 sb2[2][AGENTS * 32];   // [pair][a*32+lane] = {b2(g_lo), b2(g_hi)}
    __shared__ float sred[NHEADS][128][3];

    const int tid = threadIdx.x;
    const int b = blockIdx.y;
    const int h = tid >> 5, lane = tid & 31;
    const int t0 = blockIdx.x * 128;

    for (int i = tid; i < NHEADS * AGENTS; i += 512) {
        scq[i] = g_cq[b * NHEADS * AGENTS + i];
        sgv[i] = g_gv[b * NHEADS * AGENTS + i];
    }
    for (int i = tid; i < 128 * AGENTS; i += 512) {
        float val = bias2[(size_t)t0 * AGENTS + i] * LOG2E;
        int n = i / AGENTS, a = i - n * AGENTS;
        int g = n >> 5, l = n & 31;
        float* dst = (float*)sb2[g >> 1];
        dst[(a * 32 + l) * 2 + (g & 1)] = val;
    }
    __syncthreads();

    // per-thread q values for 4 token groups, packed pairwise
    u64 qp[2][3];
    #pragma unroll
    for (int p = 0; p < 2; p++) {
        const float* qa = Qg_all + (size_t)b * NTOK * 3 + (t0 + (2 * p) * 32 + lane) * 3;
        const float* qb = Qg_all + (size_t)b * NTOK * 3 + (t0 + (2 * p + 1) * 32 + lane) * 3;
        qp[p][0] = pack2(qa[0], qb[0]);
        qp[p][1] = pack2(qa[1], qb[1]);
        qp[p][2] = pack2(qa[2], qb[2]);
    }

    u64 su2[2], u02[2], u12[2], u22[2];
    u64 zero = pack2(0.f, 0.f);
    #pragma unroll
    for (int p = 0; p < 2; p++) { su2[p] = zero; u02[p] = zero; u12[p] = zero; u22[p] = zero; }

    const float4* cqh = scq + h * AGENTS;
    const float4* gvh = sgv + h * AGENTS;
    #pragma unroll 7
    for (int a = 0; a < AGENTS; a++) {
        float4 cq = cqh[a];
        float4 gv = gvh[a];
        u64 cqx = pack2(cq.x, cq.x), cqy = pack2(cq.y, cq.y);
        u64 cqz = pack2(cq.z, cq.z), cqw = pack2(cq.w, cq.w);
        u64 gx = pack2(gv.x, gv.x), gy = pack2(gv.y, gv.y), gz = pack2(gv.z, gv.z);
        #pragma unroll
        for (int p = 0; p < 2; p++) {
            u64 b2p = *reinterpret_cast<const u64*>(&sb2[p][a * 32 + lane]);
            u64 s2 = add2(cqw, b2p);
            s2 = fma2(cqx, qp[p][0], s2);
            s2 = fma2(cqy, qp[p][1], s2);
            s2 = fma2(cqz, qp[p][2], s2);
            float slo, shi;
            unpack2(s2, slo, shi);
            u64 e2 = pack2(ex2(slo), ex2(shi));
            su2[p] = add2(su2[p], e2);
            u02[p] = fma2(e2, gx, u02[p]);
            u12[p] = fma2(e2, gy, u12[p]);
            u22[p] = fma2(e2, gz, u22[p]);
        }
    }

    #pragma unroll
    for (int p = 0; p < 2; p++) {
        float s0, s1;
        unpack2(su2[p], s0, s1);
        float i0 = 1.f / s0, i1 = 1.f / s1;
        float a0, a1;
        unpack2(u02[p], a0, a1);
        sred[h][(2 * p) * 32 + lane][0] = a0 * i0;
        sred[h][(2 * p + 1) * 32 + lane][0] = a1 * i1;
        unpack2(u12[p], a0, a1);
        sred[h][(2 * p) * 32 + lane][1] = a0 * i0;
        sred[h][(2 * p + 1) * 32 + lane][1] = a1 * i1;
        unpack2(u22[p], a0, a1);
        sred[h][(2 * p) * 32 + lane][2] = a0 * i0;
        sred[h][(2 * p + 1) * 32 + lane][2] = a1 * i1;
    }
    __syncthreads();

    if (tid < 384) {
        int j = tid >> 7, rem = tid & 127;
        int nn = t0 + rem;
        float r = g_Const[j];
        #pragma unroll
        for (int hh = 0; hh < NHEADS; hh++) r += sred[hh][rem][j];
        const float* Vb = Vg_all + (size_t)b * NTOK * 3;
        #pragma unroll
        for (int t = 0; t < 3; t++) {
            int mrow = nn - 1 + t;
            if (mrow >= 0 && mrow < NTOK) {
                const float* vp = Vb + mrow * 3;
                r += g_Ebt[t][j];
                r = fmaf(vp[0], g_Et[t][0][j], r);
                r = fmaf(vp[1], g_Et[t][1][j], r);
                r = fmaf(vp[2], g_Et[t][2][j], r);
            }
        }
        out[(size_t)b * 3 * NTOK + j * NTOK + nn] = r;
    }
}

extern "C" void kernel_launch(void* const* d_in, const int* in_sizes, int n_in,
                              void* d_out, int out_size) {
    const float* Q      = (const float*)d_in[0];
    const float* K      = (const float*)d_in[1];
    const float* V      = (const float*)d_in[2];
    const float* w_vel  = (const float*)d_in[3];
    const float* b_vel  = (const float*)d_in[4];
    const float* w_init = (const float*)d_in[5];
    const float* b_init = (const float*)d_in[6];
    const float* wq     = (const float*)d_in[7];
    const float* bq     = (const float*)d_in[8];
    const float* wk     = (const float*)d_in[9];
    const float* bk     = (const float*)d_in[10];
    const float* wv     = (const float*)d_in[11];
    const float* bv     = (const float*)d_in[12];
    const float* ab1    = (const float*)d_in[13];
    const float* ab2    = (const float*)d_in[14];
    const float* dwc_w  = (const float*)d_in[15];
    const float* dwc_b  = (const float*)d_in[16];
    const float* w_proj = (const float*)d_in[17];
    const float* b_proj = (const float*)d_in[18];
    float* out = (float*)d_out;

    prepA<<<dim3(4, 16, 3), 256>>>(w_vel, b_vel, w_init, b_init, wq, wk, wv);
    prepB<<<112, 256>>>(Q, bq, bk, bv, ab1, dwc_w, dwc_b, w_proj, b_proj);
    stage1<<<dim3(NHEADS, BATCH), 256>>>(K, V);
    stage2<<<dim3(8, BATCH), 512>>>(Q, V, ab2, out);
}